// round 4
// baseline (speedup 1.0000x reference)
#include <cuda_runtime.h>

#define Bc 4
#define Lc 1024
#define Hc 8
#define Ec 64
#define BHc 32

// d_out packing (floats): V [B,L,H,E] | series [B,H,L,L] | prior [B,H,L,L] | sig [B,H,L,1]
#define OFF_SERIES 2097152
#define OFF_PRIOR  35651584
#define OFF_SIG    69206016

// scratch: p_density [B,H,L,E] (8 MB)
__device__ float g_p[BHc * Lc * Ec];

// ---------------------------------------------------------------------------
// Kernel 1: sig + p_density.  256 threads = 4 rows x 64 e.  grid = BH*L/4.
// sig chain in double at the reference's f32 rounding points (bitwise-matches
// XLA sigmoid/pow); p chain replicates the f32 op sequence with _rn ops.
// ---------------------------------------------------------------------------
__global__ void __launch_bounds__(256) sig_p_kernel(const float* __restrict__ sigma,
                                                    const float* __restrict__ x,
                                                    float* __restrict__ out) {
    __shared__ float s_sig[4];
    int e    = threadIdx.x & 63;
    int rsub = threadIdx.x >> 6;
    int row  = blockIdx.x * 4 + rsub;   // (b*H + h)*L + l
    int l    = row & (Lc - 1);
    int bh   = row >> 10;
    int b    = bh >> 3, h = bh & 7;

    if (e == 0) {
        float t = __fmul_rn(sigma[(b * Lc + l) * Hc + h], 5.0f);   // ref: sigma*5.0 (f32)
        double sd = 1.0 / (1.0 + exp(-(double)t));                 // sigmoid, correctly rounded
        float s = (float)sd;
        s = __fadd_rn(s, 1e-5f);                                   // ref: +1e-5 (f32)
        float p3 = (float)exp((double)s * 1.0986122886681098);     // 3^s, correctly rounded
        float sg = __fadd_rn(p3, -1.0f);                           // ref: -1.0 (f32)
        s_sig[rsub] = sg;
        out[OFF_SIG + row] = sg;
    }
    __syncthreads();
    float sg = s_sig[rsub];

    float xv  = x[((size_t)(b * Lc + l) * Hc + h) * Ec + e];
    float xsq = __fmul_rn(xv, xv);
    float s2  = __fmul_rn(sg, sg);
    float dnm = __fadd_rn(s2, s2);
    float a   = __fdiv_rn(xsq, dnm);
    float ex  = expf(-a);
    float cf  = __fdiv_rn(0.3989422804014327f, sg);
    float pd  = __fadd_rn(__fmul_rn(cf, ex), 1e-5f);
    g_p[(size_t)row * Ec + e] = pd;
}

// ---------------------------------------------------------------------------
// Kernel 2: prior = P @ P^T per (b,h), SYMMETRIC: only tiles bi<=bj computed
// (36 of 64), mirror written via smem transpose staging.
// 256 threads = 8 warps. Warp w: rows 64*(w>>2)+[0..63] (broadcast operand),
// cols 32*(w&3)+lane (per-lane LDS.128, pitch 68 -> conflict-free).
// ---------------------------------------------------------------------------
__global__ void __launch_bounds__(256) prior_kernel(float* __restrict__ out) {
    extern __shared__ float sm[];
    float* Ar = sm;             // [128][68]
    float* Bn = sm + 128 * 68;  // [128][68]

    int tid = threadIdx.x;
    int bh  = blockIdx.y;

    // map linear tile index -> (bi, bj), bi <= bj
    int bi = 0, rem = blockIdx.x;
    while (rem >= 8 - bi) { rem -= 8 - bi; bi++; }
    int bj = bi + rem;

    const float* P = g_p + (size_t)bh * Lc * Ec;

    for (int f = tid; f < 2048; f += 256) {
        int r = f >> 4, eq = f & 15;
        *(float4*)&Ar[r * 68 + eq * 4] = *(const float4*)&P[(size_t)(bi * 128 + r) * 64 + eq * 4];
        *(float4*)&Bn[r * 68 + eq * 4] = *(const float4*)&P[(size_t)(bj * 128 + r) * 64 + eq * 4];
    }
    __syncthreads();

    int w = tid >> 5, lane = tid & 31;
    int colb = 32 * (w & 3);
    int rowb = 64 * (w >> 2);

    float acc[64];
#pragma unroll
    for (int i = 0; i < 64; i++) acc[i] = 0.0f;

    for (int k4 = 0; k4 < 16; k4++) {
        float4 b4 = *(float4*)&Bn[(colb + lane) * 68 + k4 * 4];
#pragma unroll
        for (int rr = 0; rr < 64; rr++) {
            float4 a4 = *(float4*)&Ar[(rowb + rr) * 68 + k4 * 4];
            acc[rr] = fmaf(a4.w, b4.w, fmaf(a4.z, b4.z,
                      fmaf(a4.y, b4.y, fmaf(a4.x, b4.x, acc[rr]))));
        }
    }

    float* o = out + OFF_PRIOR + (size_t)bh * Lc * Lc;
    int col = bj * 128 + colb + lane;
#pragma unroll
    for (int rr = 0; rr < 64; rr++) {
        int rowg = bi * 128 + rowb + rr;
        o[(size_t)rowg * Lc + col] = acc[rr];   // coalesced: lanes -> consecutive cols
    }

    if (bi != bj) {
        // mirror tile (bj,bi): transpose via smem staging, pitch 129 (STS conflict-free)
        __syncthreads();               // done reading Ar/Bn
        float* T = sm;                 // [128][129] = 66,048 B < 69,632 B
        int tr = colb + lane;          // transposed row = original col (local)
#pragma unroll
        for (int rr = 0; rr < 64; rr++)
            T[tr * 129 + rowb + rr] = acc[rr];
        __syncthreads();
        // coalesced writeback: assemble float4 from 4 scalar LDS (conflict-free)
        for (int f = tid; f < 4096; f += 256) {
            int r = f >> 5, c4 = (f & 31) * 4;
            float4 v4 = make_float4(T[r * 129 + c4], T[r * 129 + c4 + 1],
                                    T[r * 129 + c4 + 2], T[r * 129 + c4 + 3]);
            *(float4*)&o[(size_t)(bj * 128 + r) * Lc + bi * 128 + c4] = v4;
        }
    }
}

// ---------------------------------------------------------------------------
// Kernel 3: fused causal attention per (bh, 32-row block). 512 threads.
// Full 32x1024 score panel in smem (pitch 1026 -> aligned float2 row reads);
// series written once; V accumulated in registers. Causal tiles skipped.
// ---------------------------------------------------------------------------
__global__ void __launch_bounds__(512) attn_kernel(const float* __restrict__ qg,
                                                   const float* __restrict__ kg,
                                                   const float* __restrict__ vg,
                                                   float* __restrict__ out) {
    extern __shared__ float sm[];
    float* Sp = sm;                  // [32][1026] score/prob panel
    float* Qr = sm + 32 * 1026;      // [32][68]
    float* Kn = Qr + 32 * 68;        // [128][68], reused for V tiles

    int tid  = threadIdx.x;
    int w    = tid >> 5, lane = tid & 31;   // 16 warps
    int rb   = 31 - blockIdx.x;      // big blocks first
    int bh   = blockIdx.y;
    int b    = bh >> 3, h = bh & 7;
    int r0   = rb * 32;
    int nt   = (rb >> 2) + 1;        // 128-wide tiles to cover s <= r0+31
    int n_s  = nt << 7;
    const float scale = 0.125f;      // 1/sqrt(64)

    // load Q rows r0..r0+31
    for (int f = tid; f < 512; f += 512) {
        int r = f >> 4, eq = f & 15;
        *(float4*)&Qr[r * 68 + eq * 4] =
            *(const float4*)&qg[((size_t)(b * Lc + r0 + r) * Hc + h) * Ec + eq * 4];
    }

    // ---- Phase 1: scores (rows = lanes, warp w owns cols w*8..w*8+7)
    for (int t = 0; t < nt; t++) {
        __syncthreads();
        int s0 = t << 7;
        for (int f = tid; f < 2048; f += 512) {
            int s = f >> 4, eq = f & 15;
            *(float4*)&Kn[s * 68 + eq * 4] =
                *(const float4*)&kg[((size_t)(b * Lc + s0 + s) * Hc + h) * Ec + eq * 4];
        }
        __syncthreads();

        float acc[8];
#pragma unroll
        for (int j = 0; j < 8; j++) acc[j] = 0.0f;

#pragma unroll 4
        for (int k4 = 0; k4 < 16; k4++) {
            float4 a4 = *(float4*)&Qr[lane * 68 + k4 * 4];   // per-lane, conflict-free
#pragma unroll
            for (int j = 0; j < 8; j++) {
                float4 b4 = *(float4*)&Kn[(w * 8 + j) * 68 + k4 * 4];  // warp-broadcast
                acc[j] = fmaf(a4.w, b4.w, fmaf(a4.z, b4.z,
                         fmaf(a4.y, b4.y, fmaf(a4.x, b4.x, acc[j]))));
            }
        }

        int l = r0 + lane;
#pragma unroll
        for (int j = 0; j < 8; j++) {
            int s = s0 + w * 8 + j;
            Sp[lane * 1026 + s] = (s <= l) ? acc[j] * scale : -3.4e38f;
        }
    }
    __syncthreads();

    // ---- Phase 2: rowwise softmax (warp w handles rows 2w, 2w+1), write series
    for (int rr = 0; rr < 2; rr++) {
        int r = w * 2 + rr;
        float* row = &Sp[r * 1026];

        float m = -3.4e38f;
        for (int s = lane; s < n_s; s += 32) m = fmaxf(m, row[s]);
#pragma unroll
        for (int o = 16; o > 0; o >>= 1) m = fmaxf(m, __shfl_xor_sync(0xffffffffu, m, o));

        float sum = 0.0f;
        for (int s = lane; s < n_s; s += 32) {
            float e = expf(row[s] - m);   // masked -> underflow to exact 0
            row[s] = e;
            sum += e;
        }
#pragma unroll
        for (int o = 16; o > 0; o >>= 1) sum += __shfl_xor_sync(0xffffffffu, sum, o);

        float inv = 1.0f / sum;
        float* g = out + OFF_SERIES + ((size_t)bh * Lc + (r0 + r)) * Lc;
        for (int s = lane; s < n_s; s += 32) {
            float p = row[s] * inv;
            row[s] = p;
            g[s] = p;                    // coalesced
        }
        for (int s = n_s + lane; s < Lc; s += 32) g[s] = 0.0f;
    }

    // ---- Phase 3: V = series @ values (warp w rows 2w..2w+1, cols = 2*lane)
    float va[2][2];
#pragma unroll
    for (int rr = 0; rr < 2; rr++) { va[rr][0] = 0.0f; va[rr][1] = 0.0f; }

    for (int t = 0; t < nt; t++) {
        __syncthreads();
        int s0 = t << 7;
        for (int f = tid; f < 2048; f += 512) {
            int s = f >> 4, eq = f & 15;
            *(float4*)&Kn[s * 68 + eq * 4] =
                *(const float4*)&vg[((size_t)(b * Lc + s0 + s) * Hc + h) * Ec + eq * 4];
        }
        __syncthreads();

#pragma unroll 4
        for (int ss = 0; ss < 128; ss += 2) {
            float2 v2a = *(float2*)&Kn[ss * 68 + 2 * lane];
            float2 v2b = *(float2*)&Kn[(ss + 1) * 68 + 2 * lane];
#pragma unroll
            for (int rr = 0; rr < 2; rr++) {
                float2 p2 = *(float2*)&Sp[(w * 2 + rr) * 1026 + s0 + ss];  // broadcast, aligned
                va[rr][0] = fmaf(p2.y, v2b.x, fmaf(p2.x, v2a.x, va[rr][0]));
                va[rr][1] = fmaf(p2.y, v2b.y, fmaf(p2.x, v2a.y, va[rr][1]));
            }
        }
    }

#pragma unroll
    for (int rr = 0; rr < 2; rr++) {
        int l = r0 + w * 2 + rr;
        *(float2*)&out[((size_t)(b * Lc + l) * Hc + h) * Ec + 2 * lane] =
            make_float2(va[rr][0], va[rr][1]);              // coalesced
    }
}

// ---------------------------------------------------------------------------
extern "C" void kernel_launch(void* const* d_in, const int* in_sizes, int n_in,
                              void* d_out, int out_size) {
    const float* q     = (const float*)d_in[0];
    const float* k     = (const float*)d_in[1];
    const float* v     = (const float*)d_in[2];
    const float* sigma = (const float*)d_in[3];
    const float* x     = (const float*)d_in[4];
    float* out = (float*)d_out;

    const int SMEM_PRIOR = 2 * 128 * 68 * 4;                       // 69,632 B
    const int SMEM_ATTN  = (32 * 1026 + 32 * 68 + 128 * 68) * 4;   // 174,848 B

    cudaFuncSetAttribute(prior_kernel, cudaFuncAttributeMaxDynamicSharedMemorySize, SMEM_PRIOR);
    cudaFuncSetAttribute(attn_kernel,  cudaFuncAttributeMaxDynamicSharedMemorySize, SMEM_ATTN);

    sig_p_kernel<<<BHc * Lc / 4, 256>>>(sigma, x, out);
    prior_kernel<<<dim3(36, BHc), 256, SMEM_PRIOR>>>(out);
    attn_kernel<<<dim3(32, BHc), 512, SMEM_ATTN>>>(q, k, v, out);
}

// round 5
// speedup vs baseline: 1.2615x; 1.2615x over previous
#include <cuda_runtime.h>

#define Bc 4
#define Lc 1024
#define Hc 8
#define Ec 64
#define BHc 32

// d_out packing (floats): V [B,L,H,E] | series [B,H,L,L] | prior [B,H,L,L] | sig [B,H,L,1]
#define OFF_SERIES 2097152
#define OFF_PRIOR  35651584
#define OFF_SIG    69206016

// scratch: p_density [B,H,L,E] (8 MB)
__device__ float g_p[BHc * Lc * Ec];

// ---------------------------------------------------------------------------
// Kernel 1: sig + p_density.  256 threads = 4 rows x 64 e.  grid = BH*L/4.
// sig chain in double at the reference's f32 rounding points.
// ---------------------------------------------------------------------------
__global__ void __launch_bounds__(256) sig_p_kernel(const float* __restrict__ sigma,
                                                    const float* __restrict__ x,
                                                    float* __restrict__ out) {
    __shared__ float s_sig[4];
    int e    = threadIdx.x & 63;
    int rsub = threadIdx.x >> 6;
    int row  = blockIdx.x * 4 + rsub;   // (b*H + h)*L + l
    int l    = row & (Lc - 1);
    int bh   = row >> 10;
    int b    = bh >> 3, h = bh & 7;

    if (e == 0) {
        float t = __fmul_rn(sigma[(b * Lc + l) * Hc + h], 5.0f);
        double sd = 1.0 / (1.0 + exp(-(double)t));
        float s = (float)sd;
        s = __fadd_rn(s, 1e-5f);
        float p3 = (float)exp((double)s * 1.0986122886681098);
        float sg = __fadd_rn(p3, -1.0f);
        s_sig[rsub] = sg;
        out[OFF_SIG + row] = sg;
    }
    __syncthreads();
    float sg = s_sig[rsub];

    float xv  = x[((size_t)(b * Lc + l) * Hc + h) * Ec + e];
    float xsq = __fmul_rn(xv, xv);
    float s2  = __fmul_rn(sg, sg);
    float dnm = __fadd_rn(s2, s2);
    float a   = __fdiv_rn(xsq, dnm);
    float ex  = expf(-a);
    float cf  = __fdiv_rn(0.3989422804014327f, sg);
    float pd  = __fadd_rn(__fmul_rn(cf, ex), 1e-5f);
    g_p[(size_t)row * Ec + e] = pd;
}

// ---------------------------------------------------------------------------
// Kernel 2: prior = P @ P^T per (b,h), symmetric: tiles bi<=bj (36 of 64),
// mirror via pitch-129 smem transpose.  256 threads = 8 warps.
// ---------------------------------------------------------------------------
__global__ void __launch_bounds__(256) prior_kernel(float* __restrict__ out) {
    extern __shared__ float sm[];
    float* Ar = sm;             // [128][68]
    float* Bn = sm + 128 * 68;  // [128][68]

    int tid = threadIdx.x;
    int bh  = blockIdx.y;

    int bi = 0, rem = blockIdx.x;
    while (rem >= 8 - bi) { rem -= 8 - bi; bi++; }
    int bj = bi + rem;

    const float* P = g_p + (size_t)bh * Lc * Ec;

    for (int f = tid; f < 2048; f += 256) {
        int r = f >> 4, eq = f & 15;
        *(float4*)&Ar[r * 68 + eq * 4] = *(const float4*)&P[(size_t)(bi * 128 + r) * 64 + eq * 4];
        *(float4*)&Bn[r * 68 + eq * 4] = *(const float4*)&P[(size_t)(bj * 128 + r) * 64 + eq * 4];
    }
    __syncthreads();

    int w = tid >> 5, lane = tid & 31;
    int colb = 32 * (w & 3);
    int rowb = 64 * (w >> 2);

    float acc[64];
#pragma unroll
    for (int i = 0; i < 64; i++) acc[i] = 0.0f;

    for (int k4 = 0; k4 < 16; k4++) {
        float4 b4 = *(float4*)&Bn[(colb + lane) * 68 + k4 * 4];
#pragma unroll
        for (int rr = 0; rr < 64; rr++) {
            float4 a4 = *(float4*)&Ar[(rowb + rr) * 68 + k4 * 4];
            acc[rr] = fmaf(a4.w, b4.w, fmaf(a4.z, b4.z,
                      fmaf(a4.y, b4.y, fmaf(a4.x, b4.x, acc[rr]))));
        }
    }

    float* o = out + OFF_PRIOR + (size_t)bh * Lc * Lc;
    int col = bj * 128 + colb + lane;
#pragma unroll
    for (int rr = 0; rr < 64; rr++) {
        int rowg = bi * 128 + rowb + rr;
        o[(size_t)rowg * Lc + col] = acc[rr];
    }

    if (bi != bj) {
        __syncthreads();
        float* T = sm;                 // [128][129]
        int tr = colb + lane;
#pragma unroll
        for (int rr = 0; rr < 64; rr++)
            T[tr * 129 + rowb + rr] = acc[rr];
        __syncthreads();
        for (int f = tid; f < 4096; f += 256) {
            int r = f >> 5, c4 = (f & 31) * 4;
            float4 v4 = make_float4(T[r * 129 + c4], T[r * 129 + c4 + 1],
                                    T[r * 129 + c4 + 2], T[r * 129 + c4 + 3]);
            *(float4*)&o[(size_t)(bj * 128 + r) * Lc + bi * 128 + c4] = v4;
        }
    }
}

// ---------------------------------------------------------------------------
// Kernel 3: fused causal attention per (bh, 16-row block). 256 threads, 8 warps.
// Panel 16x1026 (104.8 KB total -> 2 CTAs/SM). Warp w owns cols [16w,16w+16);
// lane: row = lane&15, colgroup = lane>>4 (8 cols each) -> 64 FMA per broadcast
// K-vector.  Causal tiles skipped; series written exactly once.
// ---------------------------------------------------------------------------
__global__ void __launch_bounds__(256) attn_kernel(const float* __restrict__ qg,
                                                   const float* __restrict__ kg,
                                                   const float* __restrict__ vg,
                                                   float* __restrict__ out) {
    extern __shared__ float sm[];
    float* Sp = sm;                  // [16][1026]
    float* Qr = sm + 16 * 1026;      // [16][68]
    float* Kn = Qr + 16 * 68;        // [128][68], reused for V tiles

    int tid  = threadIdx.x;
    int w    = tid >> 5, lane = tid & 31;
    int rb   = 63 - blockIdx.x;      // big blocks first
    int bh   = blockIdx.y;
    int b    = bh >> 3, h = bh & 7;
    int r0   = rb * 16;
    int nt   = (rb >> 3) + 1;        // 128-wide tiles to cover s <= r0+15
    int n_s  = nt << 7;
    const float scale = 0.125f;      // 1/sqrt(64)

    // load Q rows r0..r0+15 (16 rows x 16 float4 = 256 -> one per thread)
    {
        int r = tid >> 4, eq = tid & 15;
        *(float4*)&Qr[r * 68 + eq * 4] =
            *(const float4*)&qg[((size_t)(b * Lc + r0 + r) * Hc + h) * Ec + eq * 4];
    }

    int row = lane & 15;             // 0..15
    int cg  = lane >> 4;             // 0/1

    // ---- Phase 1: scores
    for (int t = 0; t < nt; t++) {
        __syncthreads();
        int s0 = t << 7;
        for (int f = tid; f < 2048; f += 256) {
            int s = f >> 4, eq = f & 15;
            *(float4*)&Kn[s * 68 + eq * 4] =
                *(const float4*)&kg[((size_t)(b * Lc + s0 + s) * Hc + h) * Ec + eq * 4];
        }
        __syncthreads();

        float acc[8];
#pragma unroll
        for (int j = 0; j < 8; j++) acc[j] = 0.0f;

#pragma unroll 4
        for (int k4 = 0; k4 < 16; k4++) {
            float4 a4 = *(float4*)&Qr[row * 68 + k4 * 4];    // 16 distinct -> 2 wavefronts
#pragma unroll
            for (int j = 0; j < 8; j++) {
                float4 b4 = *(float4*)&Kn[(w * 16 + cg * 8 + j) * 68 + k4 * 4]; // 2 addrs/warp
                acc[j] = fmaf(a4.w, b4.w, fmaf(a4.z, b4.z,
                         fmaf(a4.y, b4.y, fmaf(a4.x, b4.x, acc[j]))));
            }
        }

        int l = r0 + row;
#pragma unroll
        for (int j = 0; j < 8; j++) {
            int s = s0 + w * 16 + cg * 8 + j;
            Sp[row * 1026 + s] = (s <= l) ? acc[j] * scale : -3.4e38f;
        }
    }
    __syncthreads();

    // ---- Phase 2: rowwise softmax (warp w rows 2w, 2w+1), write series
    for (int rr = 0; rr < 2; rr++) {
        int r = w * 2 + rr;
        float* rowp = &Sp[r * 1026];

        float m = -3.4e38f;
        for (int s = lane; s < n_s; s += 32) m = fmaxf(m, rowp[s]);
#pragma unroll
        for (int o = 16; o > 0; o >>= 1) m = fmaxf(m, __shfl_xor_sync(0xffffffffu, m, o));

        float sum = 0.0f;
        for (int s = lane; s < n_s; s += 32) {
            float e = expf(rowp[s] - m);
            rowp[s] = e;
            sum += e;
        }
#pragma unroll
        for (int o = 16; o > 0; o >>= 1) sum += __shfl_xor_sync(0xffffffffu, sum, o);

        float inv = 1.0f / sum;
        float* g = out + OFF_SERIES + ((size_t)bh * Lc + (r0 + r)) * Lc;
        for (int s = lane; s < n_s; s += 32) {
            float p = rowp[s] * inv;
            rowp[s] = p;
            g[s] = p;
        }
        for (int s = n_s + lane; s < Lc; s += 32) g[s] = 0.0f;
    }

    // ---- Phase 3: V = series @ values (warp w rows 2w..2w+1, cols = 2*lane)
    float va[2][2];
#pragma unroll
    for (int rr = 0; rr < 2; rr++) { va[rr][0] = 0.0f; va[rr][1] = 0.0f; }

    for (int t = 0; t < nt; t++) {
        __syncthreads();
        int s0 = t << 7;
        for (int f = tid; f < 2048; f += 256) {
            int s = f >> 4, eq = f & 15;
            *(float4*)&Kn[s * 68 + eq * 4] =
                *(const float4*)&vg[((size_t)(b * Lc + s0 + s) * Hc + h) * Ec + eq * 4];
        }
        __syncthreads();

#pragma unroll 4
        for (int ss = 0; ss < 128; ss += 2) {
            float2 v2a = *(float2*)&Kn[ss * 68 + 2 * lane];
            float2 v2b = *(float2*)&Kn[(ss + 1) * 68 + 2 * lane];
#pragma unroll
            for (int rr = 0; rr < 2; rr++) {
                float2 p2 = *(float2*)&Sp[(w * 2 + rr) * 1026 + s0 + ss];  // broadcast, aligned
                va[rr][0] = fmaf(p2.y, v2b.x, fmaf(p2.x, v2a.x, va[rr][0]));
                va[rr][1] = fmaf(p2.y, v2b.y, fmaf(p2.x, v2a.y, va[rr][1]));
            }
        }
    }

#pragma unroll
    for (int rr = 0; rr < 2; rr++) {
        int l = r0 + w * 2 + rr;
        *(float2*)&out[((size_t)(b * Lc + l) * Hc + h) * Ec + 2 * lane] =
            make_float2(va[rr][0], va[rr][1]);
    }
}

// ---------------------------------------------------------------------------
extern "C" void kernel_launch(void* const* d_in, const int* in_sizes, int n_in,
                              void* d_out, int out_size) {
    const float* q     = (const float*)d_in[0];
    const float* k     = (const float*)d_in[1];
    const float* v     = (const float*)d_in[2];
    const float* sigma = (const float*)d_in[3];
    const float* x     = (const float*)d_in[4];
    float* out = (float*)d_out;

    const int SMEM_PRIOR = 2 * 128 * 68 * 4;                        // 69,632 B
    const int SMEM_ATTN  = (16 * 1026 + 16 * 68 + 128 * 68) * 4;    // 104,832 B -> 2 CTAs/SM

    static cudaStream_t s_side = nullptr;
    static cudaEvent_t ev_fork = nullptr, ev_join = nullptr;
    if (s_side == nullptr) {
        cudaStreamCreateWithFlags(&s_side, cudaStreamNonBlocking);
        cudaEventCreateWithFlags(&ev_fork, cudaEventDisableTiming);
        cudaEventCreateWithFlags(&ev_join, cudaEventDisableTiming);
        cudaFuncSetAttribute(prior_kernel, cudaFuncAttributeMaxDynamicSharedMemorySize, SMEM_PRIOR);
        cudaFuncSetAttribute(attn_kernel,  cudaFuncAttributeMaxDynamicSharedMemorySize, SMEM_ATTN);
    }

    // Fork: sig->prior chain on side stream, attention on the main (capture) stream.
    cudaEventRecord(ev_fork, 0);
    cudaStreamWaitEvent(s_side, ev_fork, 0);

    sig_p_kernel<<<BHc * Lc / 4, 256, 0, s_side>>>(sigma, x, out);
    prior_kernel<<<dim3(36, BHc), 256, SMEM_PRIOR, s_side>>>(out);

    attn_kernel<<<dim3(64, BHc), 256, SMEM_ATTN>>>(q, k, v, out);

    // Join side stream back into the capture stream.
    cudaEventRecord(ev_join, s_side);
    cudaStreamWaitEvent(0, ev_join, 0);
}